// round 1
// baseline (speedup 1.0000x reference)
#include <cuda_runtime.h>

// Problem constants (fixed by the reference)
#define T_TOK  4096     // B*S tokens
#define DMODEL 1024
#define DFF    4096
#define NEXP   8
#define TOPK   2

// GEMM tiling
#define BM 128
#define BN 128
#define BK 8
#define TM 8
#define TN 8

// ---------------------------------------------------------------------------
// Scratch (static __device__ arrays; no allocation allowed)
// ---------------------------------------------------------------------------
__device__ int   g_cnt[NEXP];                 // tokens routed to each expert
__device__ int   g_list[NEXP][T_TOK];         // slot ids (t*2+k) per expert
__device__ float g_wt[NEXP][T_TOK];           // renormalized gate weight per entry
__device__ float g_h[(size_t)T_TOK * TOPK * DFF];    // 8192 x 4096 fp32 (134 MB)
__device__ float g_y[(size_t)T_TOK * TOPK * DMODEL]; // 8192 x 1024 fp32 (33 MB)

// ---------------------------------------------------------------------------
// Kernel 0: zero per-expert counters (graph replays need fresh counters)
// ---------------------------------------------------------------------------
__global__ void zero_cnt_kernel() {
    if (threadIdx.x < NEXP) g_cnt[threadIdx.x] = 0;
}

// ---------------------------------------------------------------------------
// Kernel 1: gating. One warp per token.
// logits = x @ Wg; top-2; weights renormalized: w0 = 1/(1+exp(l1-l0)).
// ---------------------------------------------------------------------------
__global__ void gate_kernel(const float* __restrict__ x,
                            const float* __restrict__ Wg) {
    int gwarp = (blockIdx.x * blockDim.x + threadIdx.x) >> 5;
    int lane  = threadIdx.x & 31;
    if (gwarp >= T_TOK) return;
    int t = gwarp;

    const float* xr = x + (size_t)t * DMODEL;
    float acc[NEXP];
#pragma unroll
    for (int e = 0; e < NEXP; e++) acc[e] = 0.f;

    for (int d = lane; d < DMODEL; d += 32) {
        float xv = xr[d];
        const float* wr = Wg + d * NEXP;
#pragma unroll
        for (int e = 0; e < NEXP; e++) acc[e] += xv * wr[e];
    }
#pragma unroll
    for (int e = 0; e < NEXP; e++) {
#pragma unroll
        for (int off = 16; off; off >>= 1)
            acc[e] += __shfl_xor_sync(0xFFFFFFFFu, acc[e], off);
    }
    if (lane == 0) {
        // top-2 (strict > matches jax top_k lowest-index tie-break)
        int i0 = 0; float l0 = acc[0];
#pragma unroll
        for (int e = 1; e < NEXP; e++) if (acc[e] > l0) { l0 = acc[e]; i0 = e; }
        int i1 = -1; float l1 = -3.0e38f;
#pragma unroll
        for (int e = 0; e < NEXP; e++)
            if (e != i0 && acc[e] > l1) { l1 = acc[e]; i1 = e; }

        float w0 = 1.0f / (1.0f + expf(l1 - l0));
        float w1 = 1.0f - w0;

        int p0 = atomicAdd(&g_cnt[i0], 1);
        g_list[i0][p0] = t * 2 + 0; g_wt[i0][p0] = w0;
        int p1 = atomicAdd(&g_cnt[i1], 1);
        g_list[i1][p1] = t * 2 + 1; g_wt[i1][p1] = w1;
    }
}

// ---------------------------------------------------------------------------
// Kernel 2: grouped GEMM1. h[slot] = relu(x[tok] @ W1[e] + b1[e])
// A = gathered x rows [cnt, 1024], B = W1[e] [1024, 4096]
// ---------------------------------------------------------------------------
__global__ __launch_bounds__(256)
void ffn1_kernel(const float* __restrict__ x,
                 const float* __restrict__ W1,
                 const float* __restrict__ b1) {
    const int e     = blockIdx.z;
    const int cnt   = g_cnt[e];
    const int mBase = blockIdx.y * BM;
    if (mBase >= cnt) return;
    const int nBase = blockIdx.x * BN;

    const float* Bp = W1 + (size_t)e * DMODEL * DFF;

    __shared__ float As[BK][BM];
    __shared__ float Bs[BK][BN];

    const int tid  = threadIdx.x;
    const int tr   = tid >> 4;            // 0..15
    const int tc   = tid & 15;            // 0..15
    const int aRow = tid >> 1;            // 0..127
    const int aCol = (tid & 1) * 4;       // 0 or 4
    const int bRow = tid >> 5;            // 0..7
    const int bCol = (tid & 31) * 4;      // 0..124

    const float* arow = nullptr;
    {
        int m = mBase + aRow;
        if (m < cnt) {
            int tok = g_list[e][m] >> 1;
            arow = x + (size_t)tok * DMODEL;
        }
    }

    float acc[TM][TN];
#pragma unroll
    for (int i = 0; i < TM; i++)
#pragma unroll
        for (int j = 0; j < TN; j++) acc[i][j] = 0.f;

    for (int k0 = 0; k0 < DMODEL; k0 += BK) {
        float4 av = arow ? *(const float4*)(arow + k0 + aCol)
                         : make_float4(0.f, 0.f, 0.f, 0.f);
        As[aCol + 0][aRow] = av.x;
        As[aCol + 1][aRow] = av.y;
        As[aCol + 2][aRow] = av.z;
        As[aCol + 3][aRow] = av.w;
        *(float4*)&Bs[bRow][bCol] =
            *(const float4*)(Bp + (size_t)(k0 + bRow) * DFF + nBase + bCol);
        __syncthreads();

#pragma unroll
        for (int k = 0; k < BK; k++) {
            float ra[TM], rb[TN];
            *(float4*)&ra[0] = *(const float4*)&As[k][tr * TM];
            *(float4*)&ra[4] = *(const float4*)&As[k][tr * TM + 4];
            *(float4*)&rb[0] = *(const float4*)&Bs[k][tc * TN];
            *(float4*)&rb[4] = *(const float4*)&Bs[k][tc * TN + 4];
#pragma unroll
            for (int i = 0; i < TM; i++)
#pragma unroll
                for (int j = 0; j < TN; j++)
                    acc[i][j] += ra[i] * rb[j];
        }
        __syncthreads();
    }

    // epilogue: bias + relu -> g_h[slot]
#pragma unroll
    for (int i = 0; i < TM; i++) {
        int mm = mBase + tr * TM + i;
        if (mm < cnt) {
            int slot = g_list[e][mm];
            float* hrow = g_h + (size_t)slot * DFF + nBase + tc * TN;
            const float* brow = b1 + e * DFF + nBase + tc * TN;
#pragma unroll
            for (int j = 0; j < TN; j += 4) {
                float4 v;
                v.x = fmaxf(acc[i][j + 0] + brow[j + 0], 0.f);
                v.y = fmaxf(acc[i][j + 1] + brow[j + 1], 0.f);
                v.z = fmaxf(acc[i][j + 2] + brow[j + 2], 0.f);
                v.w = fmaxf(acc[i][j + 3] + brow[j + 3], 0.f);
                *(float4*)(hrow + j) = v;
            }
        }
    }
}

// ---------------------------------------------------------------------------
// Kernel 3: grouped GEMM2. y[slot] = w * (h[slot] @ W2[e] + b2[e])
// A = gathered h rows [cnt, 4096], B = W2[e] [4096, 1024]
// ---------------------------------------------------------------------------
__global__ __launch_bounds__(256)
void ffn2_kernel(const float* __restrict__ W2,
                 const float* __restrict__ b2) {
    const int e     = blockIdx.z;
    const int cnt   = g_cnt[e];
    const int mBase = blockIdx.y * BM;
    if (mBase >= cnt) return;
    const int nBase = blockIdx.x * BN;

    const float* Bp = W2 + (size_t)e * DFF * DMODEL;

    __shared__ float As[BK][BM];
    __shared__ float Bs[BK][BN];

    const int tid  = threadIdx.x;
    const int tr   = tid >> 4;
    const int tc   = tid & 15;
    const int aRow = tid >> 1;
    const int aCol = (tid & 1) * 4;
    const int bRow = tid >> 5;
    const int bCol = (tid & 31) * 4;

    const float* arow = nullptr;
    {
        int m = mBase + aRow;
        if (m < cnt) {
            int slot = g_list[e][m];
            arow = g_h + (size_t)slot * DFF;
        }
    }

    float acc[TM][TN];
#pragma unroll
    for (int i = 0; i < TM; i++)
#pragma unroll
        for (int j = 0; j < TN; j++) acc[i][j] = 0.f;

    for (int k0 = 0; k0 < DFF; k0 += BK) {
        float4 av = arow ? *(const float4*)(arow + k0 + aCol)
                         : make_float4(0.f, 0.f, 0.f, 0.f);
        As[aCol + 0][aRow] = av.x;
        As[aCol + 1][aRow] = av.y;
        As[aCol + 2][aRow] = av.z;
        As[aCol + 3][aRow] = av.w;
        *(float4*)&Bs[bRow][bCol] =
            *(const float4*)(Bp + (size_t)(k0 + bRow) * DMODEL + nBase + bCol);
        __syncthreads();

#pragma unroll
        for (int k = 0; k < BK; k++) {
            float ra[TM], rb[TN];
            *(float4*)&ra[0] = *(const float4*)&As[k][tr * TM];
            *(float4*)&ra[4] = *(const float4*)&As[k][tr * TM + 4];
            *(float4*)&rb[0] = *(const float4*)&Bs[k][tc * TN];
            *(float4*)&rb[4] = *(const float4*)&Bs[k][tc * TN + 4];
#pragma unroll
            for (int i = 0; i < TM; i++)
#pragma unroll
                for (int j = 0; j < TN; j++)
                    acc[i][j] += ra[i] * rb[j];
        }
        __syncthreads();
    }

    // epilogue: bias, fold gate weight -> g_y[slot]
#pragma unroll
    for (int i = 0; i < TM; i++) {
        int mm = mBase + tr * TM + i;
        if (mm < cnt) {
            int slot = g_list[e][mm];
            float w  = g_wt[e][mm];
            float* yrow = g_y + (size_t)slot * DMODEL + nBase + tc * TN;
            const float* brow = b2 + e * DMODEL + nBase + tc * TN;
#pragma unroll
            for (int j = 0; j < TN; j += 4) {
                float4 v;
                v.x = w * (acc[i][j + 0] + brow[j + 0]);
                v.y = w * (acc[i][j + 1] + brow[j + 1]);
                v.z = w * (acc[i][j + 2] + brow[j + 2]);
                v.w = w * (acc[i][j + 3] + brow[j + 3]);
                *(float4*)(yrow + j) = v;
            }
        }
    }
}

// ---------------------------------------------------------------------------
// Kernel 4: combine. out[t] = y[2t] + y[2t+1]
// ---------------------------------------------------------------------------
__global__ void combine_kernel(float* __restrict__ out) {
    const int VPR = DMODEL / 4;  // float4s per row = 256
    int i = blockIdx.x * blockDim.x + threadIdx.x;
    if (i >= T_TOK * VPR) return;
    int t = i / VPR;
    int c = i % VPR;
    const float4* y4 = (const float4*)g_y;
    float4 a = y4[(size_t)(2 * t) * VPR + c];
    float4 b = y4[(size_t)(2 * t + 1) * VPR + c];
    float4 r;
    r.x = a.x + b.x; r.y = a.y + b.y; r.z = a.z + b.z; r.w = a.w + b.w;
    ((float4*)out)[i] = r;
}

// ---------------------------------------------------------------------------
// Launch
// ---------------------------------------------------------------------------
extern "C" void kernel_launch(void* const* d_in, const int* in_sizes, int n_in,
                              void* d_out, int out_size) {
    const float* x  = (const float*)d_in[0];
    const float* Wg = (const float*)d_in[1];
    const float* W1 = (const float*)d_in[2];
    const float* b1 = (const float*)d_in[3];
    const float* W2 = (const float*)d_in[4];
    const float* b2 = (const float*)d_in[5];
    float* out = (float*)d_out;

    zero_cnt_kernel<<<1, 32>>>();
    gate_kernel<<<T_TOK / 8, 256>>>(x, Wg);   // 8 warps (tokens) per block

    dim3 g1(DFF / BN, T_TOK / BM, NEXP);      // (32, 32, 8); idle m-tiles exit
    ffn1_kernel<<<g1, 256>>>(x, W1, b1);

    dim3 g2(DMODEL / BN, T_TOK / BM, NEXP);   // (8, 32, 8)
    ffn2_kernel<<<g2, 256>>>(W2, b2);

    combine_kernel<<<(T_TOK * (DMODEL / 4) + 255) / 256, 256>>>(out);
}